// round 11
// baseline (speedup 1.0000x reference)
#include <cuda_runtime.h>
#include <cuda_fp16.h>
#include <cstdint>

#define NPTS 65536
#define NE 8
#define DIN 90
#define NH 256
#define DOUT 4
#define XROW 93
#define TILE_P 128
#define KPAD 96
#define THREADS 512
#define GRID_P 148

// ---- smem map (bytes); total = 232,448 = 227KB opt-in max ----
#define SH_W2   0          // W2T [256 n][512B k], XOR(n&7) chunk swizzle, conflict-free
#define SH_W1   131072     // W1T [256 n][192B k], XOR(n&3) (2-way ldsm conflict, accepted)
#define SH_F    180224     // F: 2 groups x [128 p][192B k], XOR(p&3)
#define SH_W3   229376     // W3 fp16 [256 j][4 o] = 2048B
#define SH_B1H  231424     // b1 fp16 [256]
#define SH_B2H  231936     // b2 fp16 [256]
#define SMEM_BYTES 232448
#define F_GRP_BYTES 24576

// -------- device scratch --------
__device__ float  g_w[NPTS * NE];
__device__ int    g_idx[NE * NPTS];
__device__ int    g_cnt[NE];
__device__ __half g_xh[NPTS * KPAD];          // [n][96]
__device__ __half g_w1t[NE * NH * KPAD];      // [e][n][96]
__device__ __half g_w2t[NE * NH * NH];        // [e][n][256]
__device__ __half g_w3h[NE * NH * DOUT];      // [e][j][4]

#define ROUTE_BLOCKS 512
#define CONV_ITEMS (NE * NH * KPAD + NE * NH * NH + NE * NH * DOUT)   // 729,088
#define CONV_BLOCKS ((CONV_ITEMS + 127) / 128)
#define PREP_BLOCKS (ROUTE_BLOCKS + CONV_BLOCKS)

// -------- PTX helpers --------
__device__ __forceinline__ uint32_t smem_u32(const void* p) {
    uint32_t a;
    asm("{ .reg .u64 t; cvta.to.shared.u64 t, %1; cvt.u32.u64 %0, t; }" : "=r"(a) : "l"(p));
    return a;
}
__device__ __forceinline__ void ldsm4(uint32_t& r0, uint32_t& r1, uint32_t& r2, uint32_t& r3,
                                      uint32_t addr) {
    asm volatile("ldmatrix.sync.aligned.m8n8.x4.shared.b16 {%0,%1,%2,%3}, [%4];"
                 : "=r"(r0), "=r"(r1), "=r"(r2), "=r"(r3) : "r"(addr));
}
__device__ __forceinline__ void mma16816(float* c, const uint32_t* a, uint32_t b0, uint32_t b1) {
    asm volatile(
        "mma.sync.aligned.m16n8k16.row.col.f32.f16.f16.f32 "
        "{%0,%1,%2,%3}, {%4,%5,%6,%7}, {%8,%9}, {%0,%1,%2,%3};"
        : "+f"(c[0]), "+f"(c[1]), "+f"(c[2]), "+f"(c[3])
        : "r"(a[0]), "r"(a[1]), "r"(a[2]), "r"(a[3]), "r"(b0), "r"(b1));
}
__device__ __forceinline__ void cpa16(uint32_t dst, const void* src) {
    asm volatile("cp.async.cg.shared.global [%0], [%1], 16;" :: "r"(dst), "l"(src));
}
__device__ __forceinline__ void cpa_commit() { asm volatile("cp.async.commit_group;"); }
__device__ __forceinline__ void cpa_wait0() { asm volatile("cp.async.wait_group 0;" ::: "memory"); }
__device__ __forceinline__ void gbar(int group) {
    asm volatile("bar.sync %0, %1;" :: "r"(group + 1), "r"(256) : "memory");
}
__device__ __forceinline__ uint32_t pack2(float a, float b) {
    __half2 h = __floats2half2_rn(a, b);
    return *(uint32_t*)&h;
}

// -------- kernel 0: counters --------
__global__ void zero_cnt_kernel() {
    if (threadIdx.x < NE) g_cnt[threadIdx.x] = 0;
}

// -------- kernel 1: fused prep (routing blocks + convert blocks) --------
__global__ void prep_kernel(const float* __restrict__ x,
                            const float* __restrict__ cent,
                            const float* __restrict__ W1,
                            const float* __restrict__ W2,
                            const float* __restrict__ W3,
                            float* __restrict__ out) {
    __shared__ float sx[128 * XROW];   // 47,616B
    const int t = threadIdx.x;

    if (blockIdx.x < ROUTE_BLOCKS) {
        const int base = blockIdx.x * 128;
        for (int i = t; i < 128 * XROW; i += 128) sx[i] = x[(size_t)base * XROW + i];
        __syncthreads();

        // routing math, one point per thread
        {
            const int p = t;
            const float px = sx[p * XROW + 0];
            const float py = sx[p * XROW + 1];
            const float pz = sx[p * XROW + 2];
            float d[NE];
            float dmin = 3.4e38f;
#pragma unroll
            for (int e = 0; e < NE; e++) {
                float dx = px - __ldg(cent + e * 3 + 0);
                float dy = py - __ldg(cent + e * 3 + 1);
                float dz = pz - __ldg(cent + e * 3 + 2);
                d[e] = sqrtf(dx * dx + dy * dy + dz * dz);
                dmin = fminf(dmin, d[e]);
            }
            float inv[NE];
            float s = 0.f;
#pragma unroll
            for (int e = 0; e < NE; e++) {
                float v = 1.0f / (d[e] + 1e-8f);
                if (d[e] > 2.0f * dmin) v = 0.f;
                inv[e] = v;
                s += v;
            }
            float rs = 1.0f / s;
            const int n = base + p;
#pragma unroll
            for (int e = 0; e < NE; e++) {
                float w = inv[e] * rs;
                g_w[n * NE + e] = w;
                if (w > 0.f) {
                    int pos = atomicAdd(&g_cnt[e], 1);
                    g_idx[e * NPTS + pos] = n;
                }
            }
            *reinterpret_cast<float4*>(out + (size_t)n * 4) = make_float4(0.f, 0.f, 0.f, 0.f);
        }

        // fp16 feature write, coalesced across the block
        for (int i = t; i < 128 * 48; i += 128) {
            int p = i / 48, kp = i - p * 48;
            int k = 2 * kp;
            float a = (k < DIN) ? sx[p * XROW + 3 + k] : 0.f;
            float b = (k + 1 < DIN) ? sx[p * XROW + 4 + k] : 0.f;
            ((__half2*)g_xh)[(size_t)(base + p) * 48 + kp] = __floats2half2_rn(a, b);
        }
    } else {
        int gid = (blockIdx.x - ROUTE_BLOCKS) * 128 + t;
        if (gid < NE * NH * KPAD) {
            int e = gid / (NH * KPAD);
            int rr = gid - e * (NH * KPAD);
            int n = rr / KPAD, k = rr - n * KPAD;
            g_w1t[gid] = (k < DIN) ? __float2half_rn(W1[(e * DIN + k) * NH + n]) : __half(0.f);
        } else if (gid < NE * NH * KPAD + NE * NH * NH) {
            int r = gid - NE * NH * KPAD;
            int e = r >> 16;
            int rr = r & 65535;
            int n = rr >> 8, k = rr & 255;
            g_w2t[r] = __float2half_rn(W2[(e << 16) + (k << 8) + n]);
        } else if (gid < CONV_ITEMS) {
            int r = gid - NE * NH * KPAD - NE * NH * NH;
            g_w3h[r] = __float2half_rn(W3[r]);
        }
    }
}

// -------- expert-resident smem load (all 512 threads) --------
__device__ __forceinline__ void load_expert(uint32_t A0, char* smb, int e, int t,
                                            const float* b1, const float* b2) {
    const int n = t >> 1, hh = t & 1;
    {   // W2T row n, half hh (16 chunks), XOR(n&7)
        const char* src = (const char*)(g_w2t + ((size_t)e * NH + n) * NH) + hh * 256;
        uint32_t rb = A0 + SH_W2 + ((uint32_t)n << 9);
#pragma unroll
        for (int j = 0; j < 16; j++) {
            int c = hh * 16 + j;
            cpa16(rb + (uint32_t)((c ^ (n & 7)) << 4), src + j * 16);
        }
    }
    {   // W1T row n, half hh (6 chunks), XOR(n&3)
        const char* src = (const char*)(g_w1t + ((size_t)e * NH + n) * KPAD) + hh * 96;
        uint32_t rb = A0 + SH_W1 + (uint32_t)n * 192;
#pragma unroll
        for (int j = 0; j < 6; j++) {
            int c = hh * 6 + j;
            cpa16(rb + (uint32_t)((c ^ (n & 3)) << 4), src + j * 16);
        }
    }
    if (t < NH) {   // W3 fp16 rows + b1 fp16
        *(uint2*)(smb + SH_W3 + t * 8) = *(const uint2*)(g_w3h + ((size_t)e * NH + t) * 4);
        ((__half*)(smb + SH_B1H))[t] = __float2half_rn(b1[e * NH + t]);
    } else {        // b2 fp16
        ((__half*)(smb + SH_B2H))[t - NH] = __float2half_rn(b2[e * NH + t - NH]);
    }
}

// -------- per-group F tile load (256 threads of the group) --------
__device__ __forceinline__ void load_F(uint32_t A0, int group, int e, int base, int cnt,
                                       int gt) {
    const int p = gt >> 1, hh = gt & 1;
    int gi = base + p;
    int real = 0;
    if (gi < cnt) real = g_idx[e * NPTS + gi];
    const char* src = (const char*)(g_xh + (size_t)real * KPAD) + hh * 96;
    uint32_t fb = A0 + SH_F + (uint32_t)group * F_GRP_BYTES + (uint32_t)p * 192;
#pragma unroll
    for (int j = 0; j < 6; j++) {
        int c = hh * 6 + j;
        cpa16(fb + (uint32_t)((c ^ (p & 3)) << 4), src + j * 16);
    }
}

// -------- kernel 2: persistent dual-group fused MLP --------
__global__ __launch_bounds__(THREADS, 1)
void mlp_persist_kernel(const float* __restrict__ b1, const float* __restrict__ b2,
                        const float* __restrict__ b3, float* __restrict__ out) {
    int tp[NE + 1], cnts[NE];
    {
        int run = 0;
#pragma unroll
        for (int e = 0; e < NE; e++) {
            tp[e] = run;
            cnts[e] = g_cnt[e];
            run += (cnts[e] + TILE_P - 1) / TILE_P;
        }
        tp[NE] = run;
    }
    const int total = tp[NE];
    const int G = gridDim.x;
    const int lo = (int)(((long long)blockIdx.x * total) / G);
    const int hi = (int)(((long long)(blockIdx.x + 1) * total) / G);

    extern __shared__ char smb[];
    const uint32_t A0 = smem_u32(smb);
    const int t = threadIdx.x;
    const int lane = t & 31;
    const int g = lane >> 2, tg = lane & 3;
    const int group = t >> 8;
    const int gt = t & 255;
    const int m0 = ((t >> 5) & 7) * 16;

    const int rowpat = (lane & 7) + ((lane >> 4) << 3);
    const int cb = (lane >> 3) & 1;
    const int arow = m0 + (lane & 15);
    const uint32_t fBase = A0 + SH_F + (uint32_t)group * F_GRP_BYTES + (uint32_t)arow * 192;
    const int alow = arow & 3;
    const int ahl = lane >> 4;

    for (int e = 0; e < NE; e++) {
        const int s0 = max(lo, tp[e]);
        const int s1 = min(hi, tp[e + 1]);
        if (s0 >= s1) continue;
        __syncthreads();                         // both groups done with old weights
        load_expert(A0, smb, e, t, b1, b2);
        cpa_commit();
        cpa_wait0();
        __syncthreads();                         // weights visible

        const int cnt = cnts[e];
        const int t0 = s0 + group;
        if (t0 < s1) {
            load_F(A0, group, e, (t0 - tp[e]) * TILE_P, cnt, gt);
            cpa_commit();
        }

        for (int tt = t0; tt < s1; tt += 2) {
            const int base = (tt - tp[e]) * TILE_P;
            cpa_wait0();
            gbar(group);                         // F ready for the whole group

            // ---- layer 1: 8 chunks of n32 -> hA[64] (fp16 A-fragments for layer 2) ----
            uint32_t hA[64];
#pragma unroll
            for (int q = 0; q < 8; q++) {
                float C[16];
#pragma unroll
                for (int i = 0; i < 16; i++) C[i] = 0.f;
                const int nr1 = q * 32 + rowpat;
                const int nr2 = nr1 + 16;
                const uint32_t b1r = A0 + SH_W1 + (uint32_t)nr1 * 192;
                const uint32_t b2r = A0 + SH_W1 + (uint32_t)nr2 * 192;
                const int x1 = nr1 & 3, x2 = nr2 & 3;
#pragma unroll
                for (int s = 0; s < 6; s++) {
                    uint32_t a[4], bA[4], bB[4];
                    const int cc = (s << 1) | cb;
                    ldsm4(a[0], a[1], a[2], a[3],
                          fBase + (uint32_t)((((s << 1) | ahl) ^ alow) << 4));
                    ldsm4(bA[0], bA[1], bA[2], bA[3], b1r + (uint32_t)((cc ^ x1) << 4));
                    ldsm4(bB[0], bB[1], bB[2], bB[3], b2r + (uint32_t)((cc ^ x2) << 4));
                    mma16816(C + 0,  a, bA[0], bA[1]);
                    mma16816(C + 4,  a, bA[2], bA[3]);
                    mma16816(C + 8,  a, bB[0], bB[1]);
                    mma16816(C + 12, a, bB[2], bB[3]);
                }
                // epilogue: bias + relu + fp16 pack into layer-2 A-frag order
                const int j0 = 32 * q + 2 * tg;
#pragma unroll
                for (int nt = 0; nt < 4; nt++) {
                    __half2 bh = *(__half2*)(smb + SH_B1H + (j0 + 8 * nt) * 2);
                    float2 bf = __half22float2(bh);
                    const float* Cc = C + 4 * nt;
                    const int s2 = 2 * q + (nt >> 1);
                    const int off = 4 * s2 + 2 * (nt & 1);
                    hA[off + 0] = pack2(fmaxf(Cc[0] + bf.x, 0.f), fmaxf(Cc[1] + bf.y, 0.f));
                    hA[off + 1] = pack2(fmaxf(Cc[2] + bf.x, 0.f), fmaxf(Cc[3] + bf.y, 0.f));
                }
            }
            gbar(group);                         // all warps done reading F

            if (tt + 2 < s1) {                   // prefetch next tile's F under layer 2
                load_F(A0, group, e, (tt + 2 - tp[e]) * TILE_P, cnt, gt);
                cpa_commit();
            }

            // ---- layer 2 + fused layer 3 (f32 FFMA) ----
            float accA[4] = {0.f, 0.f, 0.f, 0.f};   // row g
            float accB[4] = {0.f, 0.f, 0.f, 0.f};   // row g+8
#pragma unroll
            for (int c2 = 0; c2 < 8; c2++) {
                float C2[16];
#pragma unroll
                for (int i = 0; i < 16; i++) C2[i] = 0.f;
                const int nr1 = c2 * 32 + rowpat;
                const int nr2 = nr1 + 16;
                const uint32_t w2r1 = A0 + SH_W2 + ((uint32_t)nr1 << 9);
                const uint32_t w2r2 = A0 + SH_W2 + ((uint32_t)nr2 << 9);
                const int x1 = nr1 & 7, x2 = nr2 & 7;
#pragma unroll
                for (int s = 0; s < 16; s++) {
                    uint32_t bA[4], bB[4];
                    const int cc = (s << 1) | cb;
                    ldsm4(bA[0], bA[1], bA[2], bA[3], w2r1 + (uint32_t)((cc ^ x1) << 4));
                    ldsm4(bB[0], bB[1], bB[2], bB[3], w2r2 + (uint32_t)((cc ^ x2) << 4));
                    const uint32_t* a = &hA[4 * s];
                    mma16816(C2 + 0,  a, bA[0], bA[1]);
                    mma16816(C2 + 4,  a, bA[2], bA[3]);
                    mma16816(C2 + 8,  a, bB[0], bB[1]);
                    mma16816(C2 + 12, a, bB[2], bB[3]);
                }
                // epilogue: h = relu(C2+b2); acc += h * W3 (f32)
                const int jb = 32 * c2 + 2 * tg;
#pragma unroll
                for (int nt = 0; nt < 4; nt++) {
                    const int jj = jb + 8 * nt;
                    __half2 bh = *(__half2*)(smb + SH_B2H + jj * 2);
                    float2 bf = __half22float2(bh);
                    const float* Cc = C2 + 4 * nt;
                    float h00 = fmaxf(Cc[0] + bf.x, 0.f);
                    float h01 = fmaxf(Cc[1] + bf.y, 0.f);
                    float h10 = fmaxf(Cc[2] + bf.x, 0.f);
                    float h11 = fmaxf(Cc[3] + bf.y, 0.f);
                    uint2 wv0 = *(uint2*)(smb + SH_W3 + jj * 8);
                    uint2 wv1 = *(uint2*)(smb + SH_W3 + (jj + 1) * 8);
                    float2 wa0 = __half22float2(*(__half2*)&wv0.x);
                    float2 wa1 = __half22float2(*(__half2*)&wv0.y);
                    float2 wb0 = __half22float2(*(__half2*)&wv1.x);
                    float2 wb1 = __half22float2(*(__half2*)&wv1.y);
                    accA[0] = fmaf(h00, wa0.x, fmaf(h01, wb0.x, accA[0]));
                    accA[1] = fmaf(h00, wa0.y, fmaf(h01, wb0.y, accA[1]));
                    accA[2] = fmaf(h00, wa1.x, fmaf(h01, wb1.x, accA[2]));
                    accA[3] = fmaf(h00, wa1.y, fmaf(h01, wb1.y, accA[3]));
                    accB[0] = fmaf(h10, wa0.x, fmaf(h11, wb0.x, accB[0]));
                    accB[1] = fmaf(h10, wa0.y, fmaf(h11, wb0.y, accB[1]));
                    accB[2] = fmaf(h10, wa1.x, fmaf(h11, wb1.x, accB[2]));
                    accB[3] = fmaf(h10, wa1.y, fmaf(h11, wb1.y, accB[3]));
                }
            }

            // ---- reduce over tg lanes (j-split) ----
#pragma unroll
            for (int o = 0; o < 4; o++) {
                accA[o] += __shfl_xor_sync(0xFFFFFFFFu, accA[o], 1);
                accA[o] += __shfl_xor_sync(0xFFFFFFFFu, accA[o], 2);
                accB[o] += __shfl_xor_sync(0xFFFFFFFFu, accB[o], 1);
                accB[o] += __shfl_xor_sync(0xFFFFFFFFu, accB[o], 2);
            }

            // ---- weighted scatter (tg==0 lanes; rows m0+g, m0+8+g) ----
            if (tg == 0) {
                const float4 b3v = __ldg(reinterpret_cast<const float4*>(b3) + e);
                int gi0 = base + m0 + g;
                int gi1 = base + m0 + 8 + g;
                if (gi0 < cnt) {
                    int n = g_idx[e * NPTS + gi0];
                    float w = __ldg(g_w + n * NE + e);
                    atomicAdd(&out[n * 4 + 0], w * (accA[0] + b3v.x));
                    atomicAdd(&out[n * 4 + 1], w * (accA[1] + b3v.y));
                    atomicAdd(&out[n * 4 + 2], w * (accA[2] + b3v.z));
                    atomicAdd(&out[n * 4 + 3], w * (accA[3] + b3v.w));
                }
                if (gi1 < cnt) {
                    int n = g_idx[e * NPTS + gi1];
                    float w = __ldg(g_w + n * NE + e);
                    atomicAdd(&out[n * 4 + 0], w * (accB[0] + b3v.x));
                    atomicAdd(&out[n * 4 + 1], w * (accB[1] + b3v.y));
                    atomicAdd(&out[n * 4 + 2], w * (accB[2] + b3v.z));
                    atomicAdd(&out[n * 4 + 3], w * (accB[3] + b3v.w));
                }
            }
        }
    }
}

// -------- launch --------
extern "C" void kernel_launch(void* const* d_in, const int* in_sizes, int n_in,
                              void* d_out, int out_size) {
    const float* x    = (const float*)d_in[0];
    const float* cent = (const float*)d_in[1];
    const float* W1   = (const float*)d_in[2];
    const float* b1   = (const float*)d_in[3];
    const float* W2   = (const float*)d_in[4];
    const float* b2   = (const float*)d_in[5];
    const float* W3   = (const float*)d_in[6];
    const float* b3   = (const float*)d_in[7];
    float* out = (float*)d_out;

    cudaFuncSetAttribute(mlp_persist_kernel, cudaFuncAttributeMaxDynamicSharedMemorySize,
                         SMEM_BYTES);

    zero_cnt_kernel<<<1, 32>>>();
    prep_kernel<<<PREP_BLOCKS, 128>>>(x, cent, W1, W2, W3, out);
    mlp_persist_kernel<<<GRID_P, THREADS, SMEM_BYTES>>>(b1, b2, b3, out);
}

// round 12
// speedup vs baseline: 1.0960x; 1.0960x over previous
#include <cuda_runtime.h>
#include <cuda_fp16.h>
#include <cstdint>

#define NPTS 65536
#define NE 8
#define DIN 90
#define NH 256
#define DOUT 4
#define XROW 93
#define TILE_P 128
#define KPAD 96
#define THREADS 256
#define GRID_P 148

// smem byte offsets (strides 208B=13*16, 528B=33*16 -> ldmatrix conflict-free)
#define SH_W1   0           // W1T [256][104h]    53,248B (expert-resident)
#define SH_W2   53248       // W2T [256][264h]   135,168B (expert-resident)
#define SH_W3T  188416      // W3T [8][264h]       4,224B (rows 0-3 data, 4-7 zero), ldsm.x2
#define SH_F    196864      // F   [128][104h]    26,624B (per tile, double-buffered idx)
#define SH_B1   223488      // b1 f32 [256]
#define SH_B2   224512      // b2 f32 [256]
#define SH_B3   225536      // b3 f32 [4]
#define SH_IDX  225552      // idx [2][128] int
#define SMEM_BYTES 226576

// -------- device scratch --------
__device__ float  g_w[NPTS * NE];
__device__ int    g_idx[NE * NPTS];
__device__ int    g_cnt[NE];
__device__ __half g_xh[NPTS * KPAD];
__device__ __half g_w1t[NE * NH * KPAD];
__device__ __half g_w2t[NE * NH * NH];

#define WCONV_TOTAL (NE * NH * KPAD + NE * NH * NH)

// -------- PTX helpers --------
__device__ __forceinline__ uint32_t smem_u32(const void* p) {
    uint32_t a;
    asm("{ .reg .u64 t; cvta.to.shared.u64 t, %1; cvt.u32.u64 %0, t; }" : "=r"(a) : "l"(p));
    return a;
}
__device__ __forceinline__ void ldsm4(uint32_t& r0, uint32_t& r1, uint32_t& r2, uint32_t& r3,
                                      uint32_t addr) {
    asm volatile("ldmatrix.sync.aligned.m8n8.x4.shared.b16 {%0,%1,%2,%3}, [%4];"
                 : "=r"(r0), "=r"(r1), "=r"(r2), "=r"(r3) : "r"(addr));
}
__device__ __forceinline__ void ldsm2(uint32_t& r0, uint32_t& r1, uint32_t addr) {
    asm volatile("ldmatrix.sync.aligned.m8n8.x2.shared.b16 {%0,%1}, [%2];"
                 : "=r"(r0), "=r"(r1) : "r"(addr));
}
__device__ __forceinline__ void mma16816(float* c, const uint32_t* a, uint32_t b0, uint32_t b1) {
    asm volatile(
        "mma.sync.aligned.m16n8k16.row.col.f32.f16.f16.f32 "
        "{%0,%1,%2,%3}, {%4,%5,%6,%7}, {%8,%9}, {%0,%1,%2,%3};"
        : "+f"(c[0]), "+f"(c[1]), "+f"(c[2]), "+f"(c[3])
        : "r"(a[0]), "r"(a[1]), "r"(a[2]), "r"(a[3]), "r"(b0), "r"(b1));
}
__device__ __forceinline__ void cpa16(uint32_t dst, const void* src) {
    asm volatile("cp.async.cg.shared.global [%0], [%1], 16;" :: "r"(dst), "l"(src));
}
__device__ __forceinline__ void cpa_commit() { asm volatile("cp.async.commit_group;"); }
__device__ __forceinline__ void cpa_wait0() { asm volatile("cp.async.wait_group 0;" ::: "memory"); }
__device__ __forceinline__ uint32_t pack2(float a, float b) {
    __half2 h = __floats2half2_rn(a, b);
    return *(uint32_t*)&h;
}

// -------- kernel 1a: weight fp16 pre-convert (W1T, W2T) + counter zero --------
__global__ void wconvert_kernel(const float* __restrict__ W1,
                                const float* __restrict__ W2) {
    int i = blockIdx.x * blockDim.x + threadIdx.x;
    if (i < NE) g_cnt[i] = 0;
    if (i < NE * NH * KPAD) {
        int e = i / (NH * KPAD);
        int rr = i - e * NH * KPAD;
        int n = rr / KPAD, k = rr - n * KPAD;
        g_w1t[i] = (k < DIN) ? __float2half_rn(W1[(e * DIN + k) * NH + n]) : __half(0.f);
    } else if (i < WCONV_TOTAL) {
        int r = i - NE * NH * KPAD;
        int e = r >> 16;
        int rr = r & 65535;
        int n = rr >> 8, k = rr & 255;
        g_w2t[r] = __float2half_rn(W2[(e << 16) + (k << 8) + n]);
    }
}

// -------- kernel 1b: routing + compaction + out zero + x fp16 convert --------
__global__ void routing_kernel(const float* __restrict__ x,
                               const float* __restrict__ cent,
                               float* __restrict__ out) {
    int n = blockIdx.x * blockDim.x + threadIdx.x;
    if (n >= NPTS) return;
    const float px = x[n * XROW + 0];
    const float py = x[n * XROW + 1];
    const float pz = x[n * XROW + 2];
    float d[NE];
    float dmin = 3.4e38f;
#pragma unroll
    for (int e = 0; e < NE; e++) {
        float dx = px - cent[e * 3 + 0];
        float dy = py - cent[e * 3 + 1];
        float dz = pz - cent[e * 3 + 2];
        d[e] = sqrtf(dx * dx + dy * dy + dz * dz);
        dmin = fminf(dmin, d[e]);
    }
    float inv[NE];
    float s = 0.f;
#pragma unroll
    for (int e = 0; e < NE; e++) {
        float v = 1.0f / (d[e] + 1e-8f);
        if (d[e] > 2.0f * dmin) v = 0.f;
        inv[e] = v;
        s += v;
    }
    float rs = 1.0f / s;
#pragma unroll
    for (int e = 0; e < NE; e++) {
        float w = inv[e] * rs;
        g_w[n * NE + e] = w;
        if (w > 0.f) {
            int pos = atomicAdd(&g_cnt[e], 1);
            g_idx[e * NPTS + pos] = n;
        }
    }
    *reinterpret_cast<float4*>(out + n * 4) = make_float4(0.f, 0.f, 0.f, 0.f);

    const float* xr = x + (size_t)n * XROW + 3;
    __half2* dst = (__half2*)(g_xh + (size_t)n * KPAD);
#pragma unroll
    for (int kp = 0; kp < 45; kp++) dst[kp] = __floats2half2_rn(xr[2 * kp], xr[2 * kp + 1]);
#pragma unroll
    for (int kp = 45; kp < 48; kp++) dst[kp] = __floats2half2_rn(0.f, 0.f);
}

// -------- tile prefetch: idx + F rows via cp.async --------
__device__ __forceinline__ void prefetch_tile(uint32_t A0, char* smb, int e, int base,
                                              int cnt, int ibuf, int t) {
    if (t < TILE_P) {
        int gi = base + t;
        int idxv = (gi < cnt) ? g_idx[e * NPTS + gi] : -1;
        ((int*)(smb + SH_IDX))[ibuf * TILE_P + t] = idxv;
        int real = idxv < 0 ? 0 : idxv;
        const char* src = (const char*)(g_xh + (size_t)real * KPAD);
        uint32_t dst = A0 + SH_F + t * 208;
#pragma unroll
        for (int j = 0; j < 12; j++) cpa16(dst + j * 16, src + j * 16);
    }
}

// -------- expert weight load (one W1T row + one W2T row per thread) --------
__device__ __forceinline__ void load_expert(uint32_t A0, char* smb, int e, int t,
                                            const float* b1, const float* b2,
                                            const float* W3, const float* b3) {
    {
        const char* src = (const char*)(g_w1t + ((size_t)e * NH + t) * KPAD);
        uint32_t dst = A0 + SH_W1 + t * 208;
#pragma unroll
        for (int j = 0; j < 12; j++) cpa16(dst + j * 16, src + j * 16);
    }
    {
        const char* src = (const char*)(g_w2t + ((size_t)e * NH + t) * NH);
        uint32_t dst = A0 + SH_W2 + t * 528;
#pragma unroll
        for (int j = 0; j < 32; j++) cpa16(dst + j * 16, src + j * 16);
    }
    if (t < 64) cpa16(A0 + SH_B1 + t * 16, (const char*)(b1 + e * NH) + t * 16);
    else if (t < 128) cpa16(A0 + SH_B2 + (t - 64) * 16, (const char*)(b2 + e * NH) + (t - 64) * 16);
    {
        __half* w3t = (__half*)(smb + SH_W3T);
        for (int i = t; i < 4 * 256; i += THREADS) {       // zero rows 4..7
            int r = i >> 8, k = i & 255;
            w3t[(4 + r) * 264 + k] = __half(0.f);
        }
        for (int i = t; i < 4 * 256; i += THREADS) {       // rows 0..3 = W3^T
            int o = i >> 8, k = i & 255;
            w3t[o * 264 + k] = __float2half_rn(W3[e * NH * DOUT + k * DOUT + o]);
        }
    }
    if (t < 4) ((float*)(smb + SH_B3))[t] = b3[e * DOUT + t];
}

// -------- kernel 2: persistent fused MLP (8 warps, m16/warp, reg-resident hA) --------
__global__ __launch_bounds__(THREADS, 1)
void mlp_persist_kernel(const float* __restrict__ b1, const float* __restrict__ b2,
                        const float* __restrict__ W3, const float* __restrict__ b3,
                        float* __restrict__ out) {
    int tp[NE + 1];
    {
        int run = 0;
#pragma unroll
        for (int e = 0; e < NE; e++) {
            tp[e] = run;
            run += (g_cnt[e] + TILE_P - 1) / TILE_P;
        }
        tp[NE] = run;
    }
    const int total = tp[NE];
    const int G = gridDim.x;
    const int lo = (int)(((long long)blockIdx.x * total) / G);
    const int hi = (int)(((long long)(blockIdx.x + 1) * total) / G);
    if (lo >= hi) return;

    extern __shared__ char smb[];
    const uint32_t A0 = smem_u32(smb);
    const int t = threadIdx.x;
    const int wid = t >> 5, lane = t & 31;
    const int g = lane >> 2, tg = lane & 3;
    const int m0 = wid * 16;

    const uint32_t aBase = A0 + SH_F + (m0 + (lane & 15)) * 208 + (lane >> 4) * 16;
    const uint32_t rowpat = (uint32_t)((lane & 7) + ((lane >> 4) << 3));
    const uint32_t colpat = (uint32_t)(((lane >> 3) & 1) * 16);
    const uint32_t bRow1 = A0 + SH_W1 + rowpat * 208 + colpat;
    const uint32_t bRow2 = A0 + SH_W2 + rowpat * 528 + colpat;
    const uint32_t wRow3 = A0 + SH_W3T + (uint32_t)(lane & 7) * 528 + colpat;

    int cur_e = -1;
    int cbuf = 0;
    {
        int e0 = 0;
#pragma unroll
        for (int k = 1; k < NE; k++) if (lo >= tp[k]) e0 = k;
        prefetch_tile(A0, smb, e0, (lo - tp[e0]) * TILE_P, g_cnt[e0], 0, t);
        cpa_commit();
    }

    for (int tt = lo; tt < hi; tt++) {
        int e = 0;
#pragma unroll
        for (int k = 1; k < NE; k++) if (tt >= tp[k]) e = k;

        cpa_wait0();
        __syncthreads();                       // F(tt)+idx ready; prev tile done
        if (e != cur_e) {
            load_expert(A0, smb, e, t, b1, b2, W3, b3);
            cpa_commit();
            cpa_wait0();
            __syncthreads();
            cur_e = e;
        }

        // ---- A1 fragment preload (then F is free) ----
        uint32_t A1[6][4];
#pragma unroll
        for (int s = 0; s < 6; s++)
            ldsm4(A1[s][0], A1[s][1], A1[s][2], A1[s][3], aBase + s * 32);
        __syncthreads();                       // F buffer free

        if (tt + 1 < hi) {
            int e2 = 0;
#pragma unroll
            for (int k = 1; k < NE; k++) if (tt + 1 >= tp[k]) e2 = k;
            prefetch_tile(A0, smb, e2, (tt + 1 - tp[e2]) * TILE_P, g_cnt[e2], cbuf ^ 1, t);
            cpa_commit();
        }

        // ---- layer 1: hA = fp16 A-fragments of relu(F@W1^T + b1) ----
        uint32_t hA[64];
#pragma unroll
        for (int qpp = 0; qpp < 8; qpp++) {
            float C[16];
#pragma unroll
            for (int i = 0; i < 16; i++) C[i] = 0.f;
            uint32_t bbA = bRow1 + (qpp * 32) * 208;
            uint32_t bbB = bbA + 16 * 208;
            uint32_t bf[2][8];
            ldsm4(bf[0][0], bf[0][1], bf[0][2], bf[0][3], bbA);
            ldsm4(bf[0][4], bf[0][5], bf[0][6], bf[0][7], bbB);
#pragma unroll
            for (int s = 0; s < 6; s++) {
                int cu = s & 1;
                if (s < 5) {
                    ldsm4(bf[cu ^ 1][0], bf[cu ^ 1][1], bf[cu ^ 1][2], bf[cu ^ 1][3],
                          bbA + (s + 1) * 32);
                    ldsm4(bf[cu ^ 1][4], bf[cu ^ 1][5], bf[cu ^ 1][6], bf[cu ^ 1][7],
                          bbB + (s + 1) * 32);
                }
                mma16816(C + 0,  A1[s], bf[cu][0], bf[cu][1]);
                mma16816(C + 4,  A1[s], bf[cu][2], bf[cu][3]);
                mma16816(C + 8,  A1[s], bf[cu][4], bf[cu][5]);
                mma16816(C + 12, A1[s], bf[cu][6], bf[cu][7]);
            }
#pragma unroll
            for (int h = 0; h < 2; h++) {
                int colb = 32 * qpp + 16 * h;
                float2 ba = *(float2*)(smb + SH_B1 + (colb + 2 * tg) * 4);
                float2 bb = *(float2*)(smb + SH_B1 + (colb + 8 + 2 * tg) * 4);
                const float* Cc = C + 8 * h;
                hA[8 * qpp + 4 * h + 0] = pack2(fmaxf(Cc[0] + ba.x, 0.f), fmaxf(Cc[1] + ba.y, 0.f));
                hA[8 * qpp + 4 * h + 1] = pack2(fmaxf(Cc[2] + ba.x, 0.f), fmaxf(Cc[3] + ba.y, 0.f));
                hA[8 * qpp + 4 * h + 2] = pack2(fmaxf(Cc[4] + bb.x, 0.f), fmaxf(Cc[5] + bb.y, 0.f));
                hA[8 * qpp + 4 * h + 3] = pack2(fmaxf(Cc[6] + bb.x, 0.f), fmaxf(Cc[7] + bb.y, 0.f));
            }
        }

        // ---- layer 2 + fused layer-3 mma ----
        float C3[4] = {0.f, 0.f, 0.f, 0.f};
#pragma unroll
        for (int qpp = 0; qpp < 8; qpp++) {
            float C[16];
#pragma unroll
            for (int i = 0; i < 16; i++) C[i] = 0.f;
            uint32_t bbA = bRow2 + (qpp * 32) * 528;
            uint32_t bbB = bbA + 16 * 528;
            uint32_t bf[2][8];
            ldsm4(bf[0][0], bf[0][1], bf[0][2], bf[0][3], bbA);
            ldsm4(bf[0][4], bf[0][5], bf[0][6], bf[0][7], bbB);
#pragma unroll
            for (int s = 0; s < 16; s++) {
                int cu = s & 1;
                if (s < 15) {
                    ldsm4(bf[cu ^ 1][0], bf[cu ^ 1][1], bf[cu ^ 1][2], bf[cu ^ 1][3],
                          bbA + (s + 1) * 32);
                    ldsm4(bf[cu ^ 1][4], bf[cu ^ 1][5], bf[cu ^ 1][6], bf[cu ^ 1][7],
                          bbB + (s + 1) * 32);
                }
                mma16816(C + 0,  &hA[4 * s], bf[cu][0], bf[cu][1]);
                mma16816(C + 4,  &hA[4 * s], bf[cu][2], bf[cu][3]);
                mma16816(C + 8,  &hA[4 * s], bf[cu][4], bf[cu][5]);
                mma16816(C + 12, &hA[4 * s], bf[cu][6], bf[cu][7]);
            }
#pragma unroll
            for (int h = 0; h < 2; h++) {
                int colb = 32 * qpp + 16 * h;
                float2 ba = *(float2*)(smb + SH_B2 + (colb + 2 * tg) * 4);
                float2 bb = *(float2*)(smb + SH_B2 + (colb + 8 + 2 * tg) * 4);
                const float* Cc = C + 8 * h;
                uint32_t a2[4];
                a2[0] = pack2(fmaxf(Cc[0] + ba.x, 0.f), fmaxf(Cc[1] + ba.y, 0.f));
                a2[1] = pack2(fmaxf(Cc[2] + ba.x, 0.f), fmaxf(Cc[3] + ba.y, 0.f));
                a2[2] = pack2(fmaxf(Cc[4] + bb.x, 0.f), fmaxf(Cc[5] + bb.y, 0.f));
                a2[3] = pack2(fmaxf(Cc[6] + bb.x, 0.f), fmaxf(Cc[7] + bb.y, 0.f));
                uint32_t w0, w1r;
                ldsm2(w0, w1r, wRow3 + (2 * qpp + h) * 32);
                mma16816(C3, a2, w0, w1r);
            }
        }

        // ---- weighted scatter (C3 cols 0-3 valid; rows m0+g, m0+8+g) ----
        if (tg < 2) {
            const int* sIdxCur = (const int*)(smb + SH_IDX) + cbuf * TILE_P;
            const float* sb3 = (const float*)(smb + SH_B3);
            int col = 2 * tg;
            float b3a = sb3[col], b3b = sb3[col + 1];
            int n0i = sIdxCur[m0 + g];
            int n1i = sIdxCur[m0 + g + 8];
            if (n0i >= 0) {
                float w = g_w[n0i * NE + e];
                atomicAdd(&out[n0i * 4 + col],     w * (C3[0] + b3a));
                atomicAdd(&out[n0i * 4 + col + 1], w * (C3[1] + b3b));
            }
            if (n1i >= 0) {
                float w = g_w[n1i * NE + e];
                atomicAdd(&out[n1i * 4 + col],     w * (C3[2] + b3a));
                atomicAdd(&out[n1i * 4 + col + 1], w * (C3[3] + b3b));
            }
        }
        cbuf ^= 1;
    }
}

// -------- launch --------
extern "C" void kernel_launch(void* const* d_in, const int* in_sizes, int n_in,
                              void* d_out, int out_size) {
    const float* x    = (const float*)d_in[0];
    const float* cent = (const float*)d_in[1];
    const float* W1   = (const float*)d_in[2];
    const float* b1   = (const float*)d_in[3];
    const float* W2   = (const float*)d_in[4];
    const float* b2   = (const float*)d_in[5];
    const float* W3   = (const float*)d_in[6];
    const float* b3   = (const float*)d_in[7];
    float* out = (float*)d_out;

    cudaFuncSetAttribute(mlp_persist_kernel, cudaFuncAttributeMaxDynamicSharedMemorySize,
                         SMEM_BYTES);

    wconvert_kernel<<<(WCONV_TOTAL + 255) / 256, 256>>>(W1, W2);   // also zeroes g_cnt
    routing_kernel<<<NPTS / 256, 256>>>(x, cent, out);
    mlp_persist_kernel<<<GRID_P, THREADS, SMEM_BYTES>>>(b1, b2, W3, b3, out);
}

// round 13
// speedup vs baseline: 1.2096x; 1.1036x over previous
#include <cuda_runtime.h>
#include <cuda_fp16.h>
#include <cstdint>

#define NPTS 65536
#define NE 8
#define DIN 90
#define NH 256
#define DOUT 4
#define XROW 93
#define TILE_P 128
#define KPAD 96
#define THREADS 256
#define GRID_P 148

// smem byte offsets (strides 208B=13*16, 528B=33*16 -> ldmatrix conflict-free)
#define SH_W1   0           // W1T [256][104h]    53,248B (expert-resident)
#define SH_W2   53248       // W2T [256][264h]   135,168B (expert-resident)
#define SH_W3T  188416      // W3T [8][264h]       4,224B (rows 0-3 data, 4-7 zero), ldsm.x2
#define SH_F    196864      // F   [128][104h]    26,624B (per tile)
#define SH_B1   223488      // b1 f32 [256]
#define SH_B2   224512      // b2 f32 [256]
#define SH_B3   225536      // b3 f32 [4]
#define SH_IDX  225552      // idx [2][128] int
#define SMEM_BYTES 226576

// -------- device scratch --------
__device__ float  g_w[NPTS * NE];
__device__ int    g_idx[NE * NPTS];
__device__ int    g_cnt[NE];
__device__ __half g_xh[NPTS * KPAD];
__device__ __half g_w1t[NE * NH * KPAD];
__device__ __half g_w2t[NE * NH * NH];

#define WCONV_TOTAL (NE * NH * KPAD + NE * NH * NH)

// -------- PTX helpers --------
__device__ __forceinline__ uint32_t smem_u32(const void* p) {
    uint32_t a;
    asm("{ .reg .u64 t; cvta.to.shared.u64 t, %1; cvt.u32.u64 %0, t; }" : "=r"(a) : "l"(p));
    return a;
}
__device__ __forceinline__ void ldsm4(uint32_t& r0, uint32_t& r1, uint32_t& r2, uint32_t& r3,
                                      uint32_t addr) {
    asm volatile("ldmatrix.sync.aligned.m8n8.x4.shared.b16 {%0,%1,%2,%3}, [%4];"
                 : "=r"(r0), "=r"(r1), "=r"(r2), "=r"(r3) : "r"(addr));
}
__device__ __forceinline__ void ldsm2(uint32_t& r0, uint32_t& r1, uint32_t addr) {
    asm volatile("ldmatrix.sync.aligned.m8n8.x2.shared.b16 {%0,%1}, [%2];"
                 : "=r"(r0), "=r"(r1) : "r"(addr));
}
__device__ __forceinline__ void mma16816(float* c, const uint32_t* a, uint32_t b0, uint32_t b1) {
    asm volatile(
        "mma.sync.aligned.m16n8k16.row.col.f32.f16.f16.f32 "
        "{%0,%1,%2,%3}, {%4,%5,%6,%7}, {%8,%9}, {%0,%1,%2,%3};"
        : "+f"(c[0]), "+f"(c[1]), "+f"(c[2]), "+f"(c[3])
        : "r"(a[0]), "r"(a[1]), "r"(a[2]), "r"(a[3]), "r"(b0), "r"(b1));
}
__device__ __forceinline__ void cpa16(uint32_t dst, const void* src) {
    asm volatile("cp.async.cg.shared.global [%0], [%1], 16;" :: "r"(dst), "l"(src));
}
__device__ __forceinline__ void cpa_commit() { asm volatile("cp.async.commit_group;"); }
__device__ __forceinline__ void cpa_wait0() { asm volatile("cp.async.wait_group 0;" ::: "memory"); }
__device__ __forceinline__ uint32_t pack2(float a, float b) {
    __half2 h = __floats2half2_rn(a, b);
    return *(uint32_t*)&h;
}

// -------- kernel 1a: weight fp16 pre-convert (W1T, W2T) + counter zero --------
__global__ void wconvert_kernel(const float* __restrict__ W1,
                                const float* __restrict__ W2) {
    int i = blockIdx.x * blockDim.x + threadIdx.x;
    if (i < NE) g_cnt[i] = 0;
    if (i < NE * NH * KPAD) {
        int e = i / (NH * KPAD);
        int rr = i - e * NH * KPAD;
        int n = rr / KPAD, k = rr - n * KPAD;
        g_w1t[i] = (k < DIN) ? __float2half_rn(W1[(e * DIN + k) * NH + n]) : __half(0.f);
    } else if (i < WCONV_TOTAL) {
        int r = i - NE * NH * KPAD;
        int e = r >> 16;
        int rr = r & 65535;
        int n = rr >> 8, k = rr & 255;
        g_w2t[r] = __float2half_rn(W2[(e << 16) + (k << 8) + n]);
    }
}

// -------- kernel 1b: routing (smem-staged, coalesced) + out zero + x fp16 --------
__global__ void routing_kernel(const float* __restrict__ x,
                               const float* __restrict__ cent,
                               float* __restrict__ out) {
    __shared__ float sx[128 * XROW];   // 47,616B
    const int t = threadIdx.x;
    const int base = blockIdx.x * 128;

    for (int i = t; i < 128 * XROW; i += 128) sx[i] = x[(size_t)base * XROW + i];
    __syncthreads();

    // routing math: one point per thread (smem reads, broadcast-friendly cent)
    {
        const int p = t;
        const float px = sx[p * XROW + 0];
        const float py = sx[p * XROW + 1];
        const float pz = sx[p * XROW + 2];
        float d[NE];
        float dmin = 3.4e38f;
#pragma unroll
        for (int e = 0; e < NE; e++) {
            float dx = px - __ldg(cent + e * 3 + 0);
            float dy = py - __ldg(cent + e * 3 + 1);
            float dz = pz - __ldg(cent + e * 3 + 2);
            d[e] = sqrtf(dx * dx + dy * dy + dz * dz);
            dmin = fminf(dmin, d[e]);
        }
        float inv[NE];
        float s = 0.f;
#pragma unroll
        for (int e = 0; e < NE; e++) {
            float v = 1.0f / (d[e] + 1e-8f);
            if (d[e] > 2.0f * dmin) v = 0.f;
            inv[e] = v;
            s += v;
        }
        float rs = 1.0f / s;
        const int n = base + p;
#pragma unroll
        for (int e = 0; e < NE; e++) {
            float w = inv[e] * rs;
            g_w[n * NE + e] = w;
            if (w > 0.f) {
                int pos = atomicAdd(&g_cnt[e], 1);
                g_idx[e * NPTS + pos] = n;
            }
        }
        *reinterpret_cast<float4*>(out + (size_t)n * 4) = make_float4(0.f, 0.f, 0.f, 0.f);
    }

    // fp16 feature emit: i-indexed, coalesced across the block
    for (int i = t; i < 128 * 48; i += 128) {
        int p = i / 48, kp = i - p * 48;
        int k = 2 * kp;
        float a = (k < DIN) ? sx[p * XROW + 3 + k] : 0.f;
        float b = (k + 1 < DIN) ? sx[p * XROW + 4 + k] : 0.f;
        ((__half2*)g_xh)[(size_t)(base + p) * 48 + kp] = __floats2half2_rn(a, b);
    }
}

// -------- tile prefetch: idx + F rows via cp.async --------
__device__ __forceinline__ void prefetch_tile(uint32_t A0, char* smb, int e, int base,
                                              int cnt, int ibuf, int t) {
    if (t < TILE_P) {
        int gi = base + t;
        int idxv = (gi < cnt) ? g_idx[e * NPTS + gi] : -1;
        ((int*)(smb + SH_IDX))[ibuf * TILE_P + t] = idxv;
        int real = idxv < 0 ? 0 : idxv;
        const char* src = (const char*)(g_xh + (size_t)real * KPAD);
        uint32_t dst = A0 + SH_F + t * 208;
#pragma unroll
        for (int j = 0; j < 12; j++) cpa16(dst + j * 16, src + j * 16);
    }
}

// -------- expert weight load --------
__device__ __forceinline__ void load_expert(uint32_t A0, char* smb, int e, int t,
                                            const float* b1, const float* b2,
                                            const float* W3, const float* b3) {
    {
        const char* src = (const char*)(g_w1t + ((size_t)e * NH + t) * KPAD);
        uint32_t dst = A0 + SH_W1 + t * 208;
#pragma unroll
        for (int j = 0; j < 12; j++) cpa16(dst + j * 16, src + j * 16);
    }
    {
        const char* src = (const char*)(g_w2t + ((size_t)e * NH + t) * NH);
        uint32_t dst = A0 + SH_W2 + t * 528;
#pragma unroll
        for (int j = 0; j < 32; j++) cpa16(dst + j * 16, src + j * 16);
    }
    if (t < 64) cpa16(A0 + SH_B1 + t * 16, (const char*)(b1 + e * NH) + t * 16);
    else if (t < 128) cpa16(A0 + SH_B2 + (t - 64) * 16, (const char*)(b2 + e * NH) + (t - 64) * 16);
    {
        __half* w3t = (__half*)(smb + SH_W3T);
        for (int i = t; i < 4 * 256; i += THREADS) {       // zero rows 4..7
            int r = i >> 8, k = i & 255;
            w3t[(4 + r) * 264 + k] = __half(0.f);
        }
        for (int i = t; i < 4 * 256; i += THREADS) {       // rows 0..3 = W3^T
            int o = i >> 8, k = i & 255;
            w3t[o * 264 + k] = __float2half_rn(W3[e * NH * DOUT + k * DOUT + o]);
        }
    }
    if (t < 4) ((float*)(smb + SH_B3))[t] = b3[e * DOUT + t];
}

// -------- kernel 2: persistent fused MLP (8 warps, m16/warp, reg-resident hA) --------
__global__ __launch_bounds__(THREADS, 1)
void mlp_persist_kernel(const float* __restrict__ b1, const float* __restrict__ b2,
                        const float* __restrict__ W3, const float* __restrict__ b3,
                        float* __restrict__ out) {
    int tp[NE + 1];
    {
        int run = 0;
#pragma unroll
        for (int e = 0; e < NE; e++) {
            tp[e] = run;
            run += (g_cnt[e] + TILE_P - 1) / TILE_P;
        }
        tp[NE] = run;
    }
    const int total = tp[NE];
    const int G = gridDim.x;
    const int lo = (int)(((long long)blockIdx.x * total) / G);
    const int hi = (int)(((long long)(blockIdx.x + 1) * total) / G);
    if (lo >= hi) return;

    extern __shared__ char smb[];
    const uint32_t A0 = smem_u32(smb);
    const int t = threadIdx.x;
    const int wid = t >> 5, lane = t & 31;
    const int g = lane >> 2, tg = lane & 3;
    const int m0 = wid * 16;

    const uint32_t aBase = A0 + SH_F + (m0 + (lane & 15)) * 208 + (lane >> 4) * 16;
    const uint32_t rowpat = (uint32_t)((lane & 7) + ((lane >> 4) << 3));
    const uint32_t colpat = (uint32_t)(((lane >> 3) & 1) * 16);
    const uint32_t bRow1 = A0 + SH_W1 + rowpat * 208 + colpat;
    const uint32_t bRow2 = A0 + SH_W2 + rowpat * 528 + colpat;
    const uint32_t wRow3 = A0 + SH_W3T + (uint32_t)(lane & 7) * 528 + colpat;

    int cur_e = -1;
    int cbuf = 0;
    {
        int e0 = 0;
#pragma unroll
        for (int k = 1; k < NE; k++) if (lo >= tp[k]) e0 = k;
        prefetch_tile(A0, smb, e0, (lo - tp[e0]) * TILE_P, g_cnt[e0], 0, t);
        cpa_commit();
    }

    for (int tt = lo; tt < hi; tt++) {
        int e = 0;
#pragma unroll
        for (int k = 1; k < NE; k++) if (tt >= tp[k]) e = k;

        cpa_wait0();
        __syncthreads();                       // F(tt)+idx ready; prev tile done
        if (e != cur_e) {
            load_expert(A0, smb, e, t, b1, b2, W3, b3);
            cpa_commit();
            cpa_wait0();
            __syncthreads();
            cur_e = e;
        }

        // ---- A1 fragment preload (then F is free) ----
        uint32_t A1[6][4];
#pragma unroll
        for (int s = 0; s < 6; s++)
            ldsm4(A1[s][0], A1[s][1], A1[s][2], A1[s][3], aBase + s * 32);
        __syncthreads();                       // F buffer free

        if (tt + 1 < hi) {
            int e2 = 0;
#pragma unroll
            for (int k = 1; k < NE; k++) if (tt + 1 >= tp[k]) e2 = k;
            prefetch_tile(A0, smb, e2, (tt + 1 - tp[e2]) * TILE_P, g_cnt[e2], cbuf ^ 1, t);
            cpa_commit();
        }

        // ---- layer 1: hA = fp16 A-fragments of relu(F@W1^T + b1) ----
        uint32_t hA[64];
#pragma unroll
        for (int qpp = 0; qpp < 8; qpp++) {
            float C[16];
#pragma unroll
            for (int i = 0; i < 16; i++) C[i] = 0.f;
            uint32_t bbA = bRow1 + (qpp * 32) * 208;
            uint32_t bbB = bbA + 16 * 208;
            uint32_t bf[2][8];
            ldsm4(bf[0][0], bf[0][1], bf[0][2], bf[0][3], bbA);
            ldsm4(bf[0][4], bf[0][5], bf[0][6], bf[0][7], bbB);
#pragma unroll
            for (int s = 0; s < 6; s++) {
                int cu = s & 1;
                if (s < 5) {
                    ldsm4(bf[cu ^ 1][0], bf[cu ^ 1][1], bf[cu ^ 1][2], bf[cu ^ 1][3],
                          bbA + (s + 1) * 32);
                    ldsm4(bf[cu ^ 1][4], bf[cu ^ 1][5], bf[cu ^ 1][6], bf[cu ^ 1][7],
                          bbB + (s + 1) * 32);
                }
                mma16816(C + 0,  A1[s], bf[cu][0], bf[cu][1]);
                mma16816(C + 4,  A1[s], bf[cu][2], bf[cu][3]);
                mma16816(C + 8,  A1[s], bf[cu][4], bf[cu][5]);
                mma16816(C + 12, A1[s], bf[cu][6], bf[cu][7]);
            }
#pragma unroll
            for (int h = 0; h < 2; h++) {
                int colb = 32 * qpp + 16 * h;
                float2 ba = *(float2*)(smb + SH_B1 + (colb + 2 * tg) * 4);
                float2 bb = *(float2*)(smb + SH_B1 + (colb + 8 + 2 * tg) * 4);
                const float* Cc = C + 8 * h;
                hA[8 * qpp + 4 * h + 0] = pack2(fmaxf(Cc[0] + ba.x, 0.f), fmaxf(Cc[1] + ba.y, 0.f));
                hA[8 * qpp + 4 * h + 1] = pack2(fmaxf(Cc[2] + ba.x, 0.f), fmaxf(Cc[3] + ba.y, 0.f));
                hA[8 * qpp + 4 * h + 2] = pack2(fmaxf(Cc[4] + bb.x, 0.f), fmaxf(Cc[5] + bb.y, 0.f));
                hA[8 * qpp + 4 * h + 3] = pack2(fmaxf(Cc[6] + bb.x, 0.f), fmaxf(Cc[7] + bb.y, 0.f));
            }
        }

        // ---- layer 2 + fused layer-3 mma ----
        float C3[4] = {0.f, 0.f, 0.f, 0.f};
#pragma unroll
        for (int qpp = 0; qpp < 8; qpp++) {
            float C[16];
#pragma unroll
            for (int i = 0; i < 16; i++) C[i] = 0.f;
            uint32_t bbA = bRow2 + (qpp * 32) * 528;
            uint32_t bbB = bbA + 16 * 528;
            uint32_t bf[2][8];
            ldsm4(bf[0][0], bf[0][1], bf[0][2], bf[0][3], bbA);
            ldsm4(bf[0][4], bf[0][5], bf[0][6], bf[0][7], bbB);
#pragma unroll
            for (int s = 0; s < 16; s++) {
                int cu = s & 1;
                if (s < 15) {
                    ldsm4(bf[cu ^ 1][0], bf[cu ^ 1][1], bf[cu ^ 1][2], bf[cu ^ 1][3],
                          bbA + (s + 1) * 32);
                    ldsm4(bf[cu ^ 1][4], bf[cu ^ 1][5], bf[cu ^ 1][6], bf[cu ^ 1][7],
                          bbB + (s + 1) * 32);
                }
                mma16816(C + 0,  &hA[4 * s], bf[cu][0], bf[cu][1]);
                mma16816(C + 4,  &hA[4 * s], bf[cu][2], bf[cu][3]);
                mma16816(C + 8,  &hA[4 * s], bf[cu][4], bf[cu][5]);
                mma16816(C + 12, &hA[4 * s], bf[cu][6], bf[cu][7]);
            }
#pragma unroll
            for (int h = 0; h < 2; h++) {
                int colb = 32 * qpp + 16 * h;
                float2 ba = *(float2*)(smb + SH_B2 + (colb + 2 * tg) * 4);
                float2 bb = *(float2*)(smb + SH_B2 + (colb + 8 + 2 * tg) * 4);
                const float* Cc = C + 8 * h;
                uint32_t a2[4];
                a2[0] = pack2(fmaxf(Cc[0] + ba.x, 0.f), fmaxf(Cc[1] + ba.y, 0.f));
                a2[1] = pack2(fmaxf(Cc[2] + ba.x, 0.f), fmaxf(Cc[3] + ba.y, 0.f));
                a2[2] = pack2(fmaxf(Cc[4] + bb.x, 0.f), fmaxf(Cc[5] + bb.y, 0.f));
                a2[3] = pack2(fmaxf(Cc[6] + bb.x, 0.f), fmaxf(Cc[7] + bb.y, 0.f));
                uint32_t w0, w1r;
                ldsm2(w0, w1r, wRow3 + (2 * qpp + h) * 32);
                mma16816(C3, a2, w0, w1r);
            }
        }

        // ---- weighted scatter (C3 cols 0-3 valid; rows m0+g, m0+8+g) ----
        if (tg < 2) {
            const int* sIdxCur = (const int*)(smb + SH_IDX) + cbuf * TILE_P;
            const float* sb3 = (const float*)(smb + SH_B3);
            int col = 2 * tg;
            float b3a = sb3[col], b3b = sb3[col + 1];
            int n0i = sIdxCur[m0 + g];
            int n1i = sIdxCur[m0 + g + 8];
            if (n0i >= 0) {
                float w = g_w[n0i * NE + e];
                atomicAdd(&out[n0i * 4 + col],     w * (C3[0] + b3a));
                atomicAdd(&out[n0i * 4 + col + 1], w * (C3[1] + b3b));
            }
            if (n1i >= 0) {
                float w = g_w[n1i * NE + e];
                atomicAdd(&out[n1i * 4 + col],     w * (C3[2] + b3a));
                atomicAdd(&out[n1i * 4 + col + 1], w * (C3[3] + b3b));
            }
        }
        cbuf ^= 1;
    }
}

// -------- launch --------
extern "C" void kernel_launch(void* const* d_in, const int* in_sizes, int n_in,
                              void* d_out, int out_size) {
    const float* x    = (const float*)d_in[0];
    const float* cent = (const float*)d_in[1];
    const float* W1   = (const float*)d_in[2];
    const float* b1   = (const float*)d_in[3];
    const float* W2   = (const float*)d_in[4];
    const float* b2   = (const float*)d_in[5];
    const float* W3   = (const float*)d_in[6];
    const float* b3   = (const float*)d_in[7];
    float* out = (float*)d_out;

    cudaFuncSetAttribute(mlp_persist_kernel, cudaFuncAttributeMaxDynamicSharedMemorySize,
                         SMEM_BYTES);

    wconvert_kernel<<<(WCONV_TOTAL + 255) / 256, 256>>>(W1, W2);   // also zeroes g_cnt
    routing_kernel<<<NPTS / 128, 128>>>(x, cent, out);
    mlp_persist_kernel<<<GRID_P, THREADS, SMEM_BYTES>>>(b1, b2, W3, b3, out);
}